// round 4
// baseline (speedup 1.0000x reference)
#include <cuda_runtime.h>
#include <cstdint>
#include <cstddef>

// ---------------------------------------------------------------------------
// Problem constants
// ---------------------------------------------------------------------------
#define BB   4
#define NYP  16384
#define NXP  4096
#define CYF  128
#define CXF  256
#define DIMF 384         // CYF + CXF
#define C1O  512
#define C2O  256
#define C3O  128
#define NTOT (BB * NYP)  // 65536
#define GM   128
#define GN   64
#define GK   16
#define MBLK (NTOT / GM) // 512 row-blocks for stats partials

// ---------------------------------------------------------------------------
// Scratch (static device allocations — allowed; runtime alloc is not)
// ---------------------------------------------------------------------------
__device__ __align__(16) float  g_F0[(size_t)NTOT * DIMF];
__device__ __align__(16) float  g_Z1[(size_t)NTOT * C1O];
__device__ __align__(16) float  g_Z2[(size_t)NTOT * C2O];
__device__ __align__(16) float  g_Z3[(size_t)NTOT * C3O];
__device__ __align__(16) float4 g_xw[BB * NXP];
__device__ __align__(16) float  g_pS[MBLK * C1O];
__device__ __align__(16) float  g_pQ[MBLK * C1O];
__device__ __align__(16) float  g_scale[3 * C1O];
__device__ __align__(16) float  g_shift[3 * C1O];

// ---------------------------------------------------------------------------
// Kernel 1: pack x points as float4 (x, y, z, ||x||^2)
// ---------------------------------------------------------------------------
__global__ void k_xw(const float* __restrict__ xp)
{
    int i = blockIdx.x * blockDim.x + threadIdx.x;
    if (i < BB * NXP) {
        float x = xp[3 * i + 0];
        float y = xp[3 * i + 1];
        float z = xp[3 * i + 2];
        g_xw[i] = make_float4(x, y, z, x * x + y * y + z * z);
    }
}

// ---------------------------------------------------------------------------
// Kernel 2: brute-force 3-NN + inverse-distance interpolation + concat
//   Writes F0[n, 0:128]  = y_feats[n]
//          F0[n, 128:384]= sum_k w_k * x_feats[idx_k]
// Top-3 scan uses d' = ||x||^2 - 2 y.x (||y||^2 added post-hoc: order-safe).
// ---------------------------------------------------------------------------
#define KT   128   // threads per block
#define KYT  2     // y points per thread
#define KYPB (KT * KYT) // 256 y points per block
#define XT   1024  // x-tile in smem

__global__ __launch_bounds__(KT)
void k_knn(const float* __restrict__ yp,
           const float* __restrict__ yf,
           const float* __restrict__ xf)
{
    __shared__ float4 sx[XT];
    __shared__ float  sw[KYPB][3];
    __shared__ int    si[KYPB][3];

    const int b     = blockIdx.y;
    const int ybase = blockIdx.x * KYPB;
    const int tid   = threadIdx.x;

    float yxv[KYT], yyv[KYT], yzv[KYT];
    float d0[KYT], d1[KYT], d2[KYT];
    int   i0[KYT], i1[KYT], i2[KYT];

#pragma unroll
    for (int u = 0; u < KYT; u++) {
        int n = ybase + tid + u * KT;
        const float* p = yp + ((size_t)b * NYP + n) * 3;
        yxv[u] = p[0]; yyv[u] = p[1]; yzv[u] = p[2];
        d0[u] = d1[u] = d2[u] = 3.0e38f;
        i0[u] = i1[u] = i2[u] = 0;
    }

    for (int t0 = 0; t0 < NXP; t0 += XT) {
        __syncthreads();
#pragma unroll
        for (int j = tid; j < XT; j += KT)
            sx[j] = g_xw[b * NXP + t0 + j];
        __syncthreads();

#pragma unroll 4
        for (int j = 0; j < XT; j++) {
            float4 xq = sx[j];
            int jg = t0 + j;
#pragma unroll
            for (int u = 0; u < KYT; u++) {
                float t = yxv[u] * xq.x;
                t = fmaf(yyv[u], xq.y, t);
                t = fmaf(yzv[u], xq.z, t);
                float dd = fmaf(-2.0f, t, xq.w);
                if (dd < d2[u]) {
                    if (dd < d1[u]) {
                        d2[u] = d1[u]; i2[u] = i1[u];
                        if (dd < d0[u]) {
                            d1[u] = d0[u]; i1[u] = i0[u];
                            d0[u] = dd;    i0[u] = jg;
                        } else {
                            d1[u] = dd;    i1[u] = jg;
                        }
                    } else {
                        d2[u] = dd; i2[u] = jg;
                    }
                }
            }
        }
    }

#pragma unroll
    for (int u = 0; u < KYT; u++) {
        int l = tid + u * KT;
        float cy = yxv[u] * yxv[u] + yyv[u] * yyv[u] + yzv[u] * yzv[u];
        float w0 = 1.0f / (d0[u] + cy + 1e-8f);
        float w1 = 1.0f / (d1[u] + cy + 1e-8f);
        float w2 = 1.0f / (d2[u] + cy + 1e-8f);
        float inv = 1.0f / (w0 + w1 + w2);
        sw[l][0] = w0 * inv; sw[l][1] = w1 * inv; sw[l][2] = w2 * inv;
        si[l][0] = i0[u];    si[l][1] = i1[u];    si[l][2] = i2[u];
    }
    __syncthreads();

    // Gather + concat (float4 vectorized); x_feats is L2-resident (4MB/batch).
    const float4* yf4 = reinterpret_cast<const float4*>(yf) + (size_t)b * NYP * (CYF / 4);
    const float4* xf4 = reinterpret_cast<const float4*>(xf) + (size_t)b * NXP * (CXF / 4);
    float4* F04 = reinterpret_cast<float4*>(g_F0) + ((size_t)b * NYP + ybase) * (DIMF / 4);
    const int C4Y = CYF / 4;   // 32
    const int C4  = DIMF / 4;  // 96

    for (int it = tid; it < KYPB * C4; it += KT) {
        int yl = it / C4;
        int c4 = it - yl * C4;
        float4 o;
        if (c4 < C4Y) {
            o = yf4[(size_t)(ybase + yl) * C4Y + c4];
        } else {
            int cc = c4 - C4Y;
            float w0 = sw[yl][0], w1 = sw[yl][1], w2 = sw[yl][2];
            float4 f0 = xf4[(size_t)si[yl][0] * (CXF / 4) + cc];
            float4 f1 = xf4[(size_t)si[yl][1] * (CXF / 4) + cc];
            float4 f2 = xf4[(size_t)si[yl][2] * (CXF / 4) + cc];
            o.x = w0 * f0.x + w1 * f1.x + w2 * f2.x;
            o.y = w0 * f0.y + w1 * f1.y + w2 * f2.y;
            o.z = w0 * f0.z + w1 * f1.z + w2 * f2.z;
            o.w = w0 * f0.w + w1 * f1.w + w2 * f2.w;
        }
        F04[(size_t)yl * C4 + c4] = o;
    }
}

// ---------------------------------------------------------------------------
// Kernel 3: tiled SGEMM  Z[n, o] = sum_c act(A[n, c]) * W[o, c]
//   act = identity (scale==null) or BN+ReLU of previous layer (fused on load).
//   Also emits deterministic per-(row-block, channel) partial sum / sumsq for
//   BatchNorm statistics. Conv bias is dropped: it cancels exactly under BN.
// Tile: 128x64, BK=16, 256 threads, 8x4 per-thread microtile.
// ---------------------------------------------------------------------------
__global__ __launch_bounds__(256, 2)
void k_gemm(const float* __restrict__ A, const float* __restrict__ Wt,
            float* __restrict__ Z, int K, int N,
            const float* __restrict__ scale, const float* __restrict__ shift,
            float* __restrict__ pS, float* __restrict__ pQ)
{
    __shared__ float As[GK][GM + 4];
    __shared__ float Bs[GK][GN + 4];
    __shared__ float sS[16][GN];
    __shared__ float sQ[16][GN];

    const int tid = threadIdx.x;
    const int nb = blockIdx.x, mb = blockIdx.y;
    const int tm = tid >> 4, tn = tid & 15;
    const int m0 = tm * 8, n0 = tn * 4;
    const size_t Abase = (size_t)mb * GM;

    float acc[8][4];
#pragma unroll
    for (int r = 0; r < 8; r++)
#pragma unroll
        for (int c = 0; c < 4; c++) acc[r][c] = 0.0f;

    for (int k0 = 0; k0 < K; k0 += GK) {
        // A tile: 128x16 = 512 float4, 2 per thread
#pragma unroll
        for (int i = 0; i < 2; i++) {
            int idx = tid + i * 256;
            int r  = idx >> 2;
            int kk = (idx & 3) * 4;
            float4 v = *reinterpret_cast<const float4*>(&A[(Abase + r) * K + k0 + kk]);
            if (scale) {
                float4 sc = *reinterpret_cast<const float4*>(&scale[k0 + kk]);
                float4 sh = *reinterpret_cast<const float4*>(&shift[k0 + kk]);
                v.x = fmaxf(fmaf(v.x, sc.x, sh.x), 0.0f);
                v.y = fmaxf(fmaf(v.y, sc.y, sh.y), 0.0f);
                v.z = fmaxf(fmaf(v.z, sc.z, sh.z), 0.0f);
                v.w = fmaxf(fmaf(v.w, sc.w, sh.w), 0.0f);
            }
            As[kk + 0][r] = v.x; As[kk + 1][r] = v.y;
            As[kk + 2][r] = v.z; As[kk + 3][r] = v.w;
        }
        // W tile: 64x16 = 256 float4, 1 per thread
        {
            int r  = tid >> 2;
            int kk = (tid & 3) * 4;
            float4 v = *reinterpret_cast<const float4*>(
                &Wt[(size_t)(nb * GN + r) * K + k0 + kk]);
            Bs[kk + 0][r] = v.x; Bs[kk + 1][r] = v.y;
            Bs[kk + 2][r] = v.z; Bs[kk + 3][r] = v.w;
        }
        __syncthreads();

#pragma unroll
        for (int k = 0; k < GK; k++) {
            float4 b4 = *reinterpret_cast<const float4*>(&Bs[k][n0]);
            float4 a0 = *reinterpret_cast<const float4*>(&As[k][m0]);
            float4 a1 = *reinterpret_cast<const float4*>(&As[k][m0 + 4]);
            float a[8] = {a0.x, a0.y, a0.z, a0.w, a1.x, a1.y, a1.z, a1.w};
            float bv[4] = {b4.x, b4.y, b4.z, b4.w};
#pragma unroll
            for (int r = 0; r < 8; r++)
#pragma unroll
                for (int c = 0; c < 4; c++)
                    acc[r][c] = fmaf(a[r], bv[c], acc[r][c]);
        }
        __syncthreads();
    }

    // Write Z
#pragma unroll
    for (int r = 0; r < 8; r++) {
        float4 v = make_float4(acc[r][0], acc[r][1], acc[r][2], acc[r][3]);
        *reinterpret_cast<float4*>(&Z[(Abase + m0 + r) * (size_t)N + nb * GN + n0]) = v;
    }

    // Deterministic per-block BN stats partials
    float s[4] = {0, 0, 0, 0}, q[4] = {0, 0, 0, 0};
#pragma unroll
    for (int r = 0; r < 8; r++)
#pragma unroll
        for (int c = 0; c < 4; c++) {
            s[c] += acc[r][c];
            q[c] += acc[r][c] * acc[r][c];
        }
#pragma unroll
    for (int c = 0; c < 4; c++) {
        sS[tm][n0 + c] = s[c];
        sQ[tm][n0 + c] = q[c];
    }
    __syncthreads();
    if (tid < GN) {
        float S = 0, Q = 0;
#pragma unroll
        for (int t = 0; t < 16; t++) { S += sS[t][tid]; Q += sQ[t][tid]; }
        pS[mb * N + nb * GN + tid] = S;
        pQ[mb * N + nb * GN + tid] = Q;
    }
}

// ---------------------------------------------------------------------------
// Kernel 4: finalize BN stats -> per-channel (scale, shift)
// ---------------------------------------------------------------------------
__global__ void k_finalize(const float* __restrict__ pS, const float* __restrict__ pQ,
                           const float* __restrict__ gma, const float* __restrict__ bet,
                           float* __restrict__ scale, float* __restrict__ shift, int N)
{
    int c = blockIdx.x, tid = threadIdx.x;
    float S = 0, Q = 0;
    for (int m = tid; m < MBLK; m += 128) { S += pS[m * N + c]; Q += pQ[m * N + c]; }
    __shared__ float rs[128], rq[128];
    rs[tid] = S; rq[tid] = Q;
    __syncthreads();
    for (int off = 64; off > 0; off >>= 1) {
        if (tid < off) { rs[tid] += rs[tid + off]; rq[tid] += rq[tid + off]; }
        __syncthreads();
    }
    if (tid == 0) {
        float mean = rs[0] * (1.0f / NTOT);
        float var  = rq[0] * (1.0f / NTOT) - mean * mean;
        float sc   = gma[c] * rsqrtf(var + 1e-5f);
        scale[c] = sc;
        shift[c] = fmaf(-mean, sc, bet[c]);
    }
}

// ---------------------------------------------------------------------------
// Kernel 5: BN3 + ReLU + transpose [n, c] -> out[b, c, n]
// ---------------------------------------------------------------------------
__global__ void k_out(const float* __restrict__ Z3, const float* __restrict__ scale,
                      const float* __restrict__ shift, float* __restrict__ out)
{
    __shared__ float tile[32][33];
    int b  = blockIdx.z;
    int n0 = blockIdx.x * 32, c0 = blockIdx.y * 32;
    int tx = threadIdx.x, ty = threadIdx.y;
    float sc = scale[c0 + tx], sh = shift[c0 + tx];
#pragma unroll
    for (int i = 0; i < 32; i += 8) {
        float v = Z3[((size_t)b * NYP + n0 + ty + i) * C3O + c0 + tx];
        tile[ty + i][tx] = fmaxf(fmaf(v, sc, sh), 0.0f);
    }
    __syncthreads();
#pragma unroll
    for (int i = 0; i < 32; i += 8)
        out[((size_t)b * C3O + c0 + ty + i) * NYP + n0 + tx] = tile[tx][ty + i];
}

// ---------------------------------------------------------------------------
// Launch
// ---------------------------------------------------------------------------
extern "C" void kernel_launch(void* const* d_in, const int* in_sizes, int n_in,
                              void* d_out, int out_size)
{
    const float* yp  = (const float*)d_in[0];
    const float* yf  = (const float*)d_in[1];
    const float* xp  = (const float*)d_in[2];
    const float* xf  = (const float*)d_in[3];
    const float* W1  = (const float*)d_in[4];
    const float* g1  = (const float*)d_in[6];
    const float* be1 = (const float*)d_in[7];
    const float* W2  = (const float*)d_in[8];
    const float* g2  = (const float*)d_in[10];
    const float* be2 = (const float*)d_in[11];
    const float* W3  = (const float*)d_in[12];
    const float* g3  = (const float*)d_in[14];
    const float* be3 = (const float*)d_in[15];
    float* out = (float*)d_out;

    float *F0, *Z1, *Z2, *Z3, *pS, *pQ, *SC, *SH;
    cudaGetSymbolAddress((void**)&F0, g_F0);
    cudaGetSymbolAddress((void**)&Z1, g_Z1);
    cudaGetSymbolAddress((void**)&Z2, g_Z2);
    cudaGetSymbolAddress((void**)&Z3, g_Z3);
    cudaGetSymbolAddress((void**)&pS, g_pS);
    cudaGetSymbolAddress((void**)&pQ, g_pQ);
    cudaGetSymbolAddress((void**)&SC, g_scale);
    cudaGetSymbolAddress((void**)&SH, g_shift);

    float* sc1 = SC + 0 * C1O;  float* sh1 = SH + 0 * C1O;
    float* sc2 = SC + 1 * C1O;  float* sh2 = SH + 1 * C1O;
    float* sc3 = SC + 2 * C1O;  float* sh3 = SH + 2 * C1O;

    // 1) pack x points
    k_xw<<<(BB * NXP + 255) / 256, 256>>>(xp);

    // 2) KNN + interpolate + concat -> F0 [NTOT, 384]
    k_knn<<<dim3(NYP / KYPB, BB), KT>>>(yp, yf, xf);

    // 3) layer 1: GEMM (raw F0) -> Z1, stats
    k_gemm<<<dim3(C1O / GN, NTOT / GM), 256>>>(F0, W1, Z1, DIMF, C1O,
                                               nullptr, nullptr, pS, pQ);
    k_finalize<<<C1O, 128>>>(pS, pQ, g1, be1, sc1, sh1, C1O);

    // 4) layer 2: GEMM with fused BN1+ReLU on load -> Z2, stats
    k_gemm<<<dim3(C2O / GN, NTOT / GM), 256>>>(Z1, W2, Z2, C1O, C2O,
                                               sc1, sh1, pS, pQ);
    k_finalize<<<C2O, 128>>>(pS, pQ, g2, be2, sc2, sh2, C2O);

    // 5) layer 3: GEMM with fused BN2+ReLU on load -> Z3, stats
    k_gemm<<<dim3(C3O / GN, NTOT / GM), 256>>>(Z2, W3, Z3, C2O, C3O,
                                               sc2, sh2, pS, pQ);
    k_finalize<<<C3O, 128>>>(pS, pQ, g3, be3, sc3, sh3, C3O);

    // 6) BN3 + ReLU + transpose -> out [B, 128, NY]
    k_out<<<dim3(NYP / 32, C3O / 32, BB), dim3(32, 8)>>>(Z3, sc3, sh3, out);
}

// round 7
// speedup vs baseline: 1.0538x; 1.0538x over previous
#include <cuda_runtime.h>
#include <cuda_bf16.h>
#include <cstdint>
#include <cstddef>

// ---------------------------------------------------------------------------
// Problem constants
// ---------------------------------------------------------------------------
#define BB   4
#define NYP  16384
#define NXP  4096
#define CYF  128
#define CXF  256
#define DIMF 384         // CYF + CXF
#define C1O  512
#define C2O  256
#define C3O  128
#define NTOT (BB * NYP)  // 65536
#define MBLK (NTOT / 128) // 512 row-blocks for stats partials

// ---------------------------------------------------------------------------
// Scratch (static device globals — runtime alloc is forbidden)
// ---------------------------------------------------------------------------
__device__ __align__(16) __nv_bfloat16 g_Ah[(size_t)NTOT * 512];
__device__ __align__(16) __nv_bfloat16 g_Al[(size_t)NTOT * 512];
__device__ __align__(16) float         g_Z [(size_t)NTOT * 512];
__device__ __align__(16) __nv_bfloat16 g_Wh[512*384 + 256*512 + 128*256];
__device__ __align__(16) __nv_bfloat16 g_Wl[512*384 + 256*512 + 128*256];
__device__ __align__(16) float4 g_xw[BB * NXP];
__device__ __align__(16) float  g_pS[MBLK * C1O];
__device__ __align__(16) float  g_pQ[MBLK * C1O];
__device__ __align__(16) float  g_scale[3 * C1O];
__device__ __align__(16) float  g_shift[3 * C1O];

// ---------------------------------------------------------------------------
// PTX helpers (base compute_103-safe: no tcgen05)
// ---------------------------------------------------------------------------
__device__ __forceinline__ uint32_t smem_u32(const void* p) {
    uint32_t a;
    asm("{ .reg .u64 t; cvta.to.shared.u64 t, %1; cvt.u32.u64 %0, t; }" : "=r"(a) : "l"(p));
    return a;
}
__device__ __forceinline__ void cpa16(uint32_t dst, const void* src) {
    asm volatile("cp.async.cg.shared.global [%0], [%1], 16;" :: "r"(dst), "l"(src));
}
#define CP_COMMIT() asm volatile("cp.async.commit_group;" ::: "memory")

#define LDSM4(r, addr) \
    asm volatile("ldmatrix.sync.aligned.m8n8.x4.shared.b16 {%0,%1,%2,%3}, [%4];" \
        : "=r"((r)[0]), "=r"((r)[1]), "=r"((r)[2]), "=r"((r)[3]) : "r"(addr))

#define MMA16816(d, a, b) \
    asm volatile("mma.sync.aligned.m16n8k16.row.col.f32.bf16.bf16.f32 " \
        "{%0,%1,%2,%3}, {%4,%5,%6,%7}, {%8,%9}, {%0,%1,%2,%3};" \
        : "+f"((d)[0]), "+f"((d)[1]), "+f"((d)[2]), "+f"((d)[3]) \
        : "r"((a)[0]), "r"((a)[1]), "r"((a)[2]), "r"((a)[3]), \
          "r"((b)[0]), "r"((b)[1]))

// bf16 hi/lo split (round-to-nearest)
__device__ __forceinline__ void bsplit(float v, unsigned short& h, unsigned short& l) {
    __nv_bfloat16 hb = __float2bfloat16_rn(v);
    float hf = __bfloat162float(hb);
    __nv_bfloat16 lb = __float2bfloat16_rn(v - hf);
    h = *reinterpret_cast<unsigned short*>(&hb);
    l = *reinterpret_cast<unsigned short*>(&lb);
}

// ---------------------------------------------------------------------------
// Kernel 1: pack x points as float4 (x, y, z, ||x||^2)
// ---------------------------------------------------------------------------
__global__ void k_xw(const float* __restrict__ xp)
{
    int i = blockIdx.x * blockDim.x + threadIdx.x;
    if (i < BB * NXP) {
        float x = xp[3 * i + 0];
        float y = xp[3 * i + 1];
        float z = xp[3 * i + 2];
        g_xw[i] = make_float4(x, y, z, x * x + y * y + z * z);
    }
}

// ---------------------------------------------------------------------------
// Kernel 2: brute-force 3-NN + interpolation + concat -> A1 (hi/lo bf16 planes)
// ---------------------------------------------------------------------------
#define KT   128
#define KYT  2
#define KYPB (KT * KYT)
#define XT   1024

__global__ __launch_bounds__(KT)
void k_knn(const float* __restrict__ yp,
           const float* __restrict__ yf,
           const float* __restrict__ xf)
{
    __shared__ float4 sx[XT];
    __shared__ float  sw[KYPB][3];
    __shared__ int    si[KYPB][3];

    const int b     = blockIdx.y;
    const int ybase = blockIdx.x * KYPB;
    const int tid   = threadIdx.x;

    float yxv[KYT], yyv[KYT], yzv[KYT];
    float d0[KYT], d1[KYT], d2[KYT];
    int   i0[KYT], i1[KYT], i2[KYT];

#pragma unroll
    for (int u = 0; u < KYT; u++) {
        int n = ybase + tid + u * KT;
        const float* p = yp + ((size_t)b * NYP + n) * 3;
        yxv[u] = p[0]; yyv[u] = p[1]; yzv[u] = p[2];
        d0[u] = d1[u] = d2[u] = 3.0e38f;
        i0[u] = i1[u] = i2[u] = 0;
    }

    for (int t0 = 0; t0 < NXP; t0 += XT) {
        __syncthreads();
        for (int j = tid; j < XT; j += KT)
            sx[j] = g_xw[b * NXP + t0 + j];
        __syncthreads();

#pragma unroll 4
        for (int j = 0; j < XT; j++) {
            float4 xq = sx[j];
            int jg = t0 + j;
#pragma unroll
            for (int u = 0; u < KYT; u++) {
                float t = yxv[u] * xq.x;
                t = fmaf(yyv[u], xq.y, t);
                t = fmaf(yzv[u], xq.z, t);
                float dd = fmaf(-2.0f, t, xq.w);
                if (dd < d2[u]) {
                    if (dd < d1[u]) {
                        d2[u] = d1[u]; i2[u] = i1[u];
                        if (dd < d0[u]) {
                            d1[u] = d0[u]; i1[u] = i0[u];
                            d0[u] = dd;    i0[u] = jg;
                        } else {
                            d1[u] = dd;    i1[u] = jg;
                        }
                    } else {
                        d2[u] = dd; i2[u] = jg;
                    }
                }
            }
        }
    }

#pragma unroll
    for (int u = 0; u < KYT; u++) {
        int l = tid + u * KT;
        float cy = yxv[u] * yxv[u] + yyv[u] * yyv[u] + yzv[u] * yzv[u];
        float w0 = 1.0f / (d0[u] + cy + 1e-8f);
        float w1 = 1.0f / (d1[u] + cy + 1e-8f);
        float w2 = 1.0f / (d2[u] + cy + 1e-8f);
        float inv = 1.0f / (w0 + w1 + w2);
        sw[l][0] = w0 * inv; sw[l][1] = w1 * inv; sw[l][2] = w2 * inv;
        si[l][0] = i0[u];    si[l][1] = i1[u];    si[l][2] = i2[u];
    }
    __syncthreads();

    const float4* yf4 = reinterpret_cast<const float4*>(yf) + (size_t)b * NYP * (CYF / 4);
    const float4* xf4 = reinterpret_cast<const float4*>(xf) + (size_t)b * NXP * (CXF / 4);
    const int C4Y = CYF / 4;   // 32
    const int C4  = DIMF / 4;  // 96

    for (int it = tid; it < KYPB * C4; it += KT) {
        int yl = it / C4;
        int c4 = it - yl * C4;
        float4 o;
        if (c4 < C4Y) {
            o = yf4[(size_t)(ybase + yl) * C4Y + c4];
        } else {
            int cc = c4 - C4Y;
            float w0 = sw[yl][0], w1 = sw[yl][1], w2 = sw[yl][2];
            float4 f0 = xf4[(size_t)si[yl][0] * (CXF / 4) + cc];
            float4 f1 = xf4[(size_t)si[yl][1] * (CXF / 4) + cc];
            float4 f2 = xf4[(size_t)si[yl][2] * (CXF / 4) + cc];
            o.x = w0 * f0.x + w1 * f1.x + w2 * f2.x;
            o.y = w0 * f0.y + w1 * f1.y + w2 * f2.y;
            o.z = w0 * f0.z + w1 * f1.z + w2 * f2.z;
            o.w = w0 * f0.w + w1 * f1.w + w2 * f2.w;
        }
        size_t nrow = (size_t)b * NYP + ybase + yl;
        ushort4 hh, ll;
        bsplit(o.x, hh.x, ll.x); bsplit(o.y, hh.y, ll.y);
        bsplit(o.z, hh.z, ll.z); bsplit(o.w, hh.w, ll.w);
        reinterpret_cast<ushort4*>(g_Ah)[nrow * C4 + c4] = hh;
        reinterpret_cast<ushort4*>(g_Al)[nrow * C4 + c4] = ll;
    }
}

// ---------------------------------------------------------------------------
// Kernel 3: weight split fp32 -> (hi, lo) bf16
// ---------------------------------------------------------------------------
__global__ void k_wconv(const float* __restrict__ W, __nv_bfloat16* __restrict__ Wh,
                        __nv_bfloat16* __restrict__ Wl, int n)
{
    int i = blockIdx.x * blockDim.x + threadIdx.x;
    if (i < n) {
        unsigned short h, l;
        bsplit(W[i], h, l);
        reinterpret_cast<unsigned short*>(Wh)[i] = h;
        reinterpret_cast<unsigned short*>(Wl)[i] = l;
    }
}

// ---------------------------------------------------------------------------
// Kernel 4: HMMA (mma.sync bf16) GEMM, bf16x3 split:
//   Z = Ah*Bh + Al*Bh + Ah*Bl   (fp32 acc; lo*lo dropped, ~1.5e-5 rel)
// Tile 128x128, BK=32, 256 threads (8 warps, 2x4), warp tile 64x32.
// 2-stage cp.async pipeline; epilogue through smem for coalesced Z stores and
// deterministic BN partial sums.
// ---------------------------------------------------------------------------
__global__ __launch_bounds__(256)
void k_gemm_mma(const __nv_bfloat16* __restrict__ Ah, const __nv_bfloat16* __restrict__ Al,
                const __nv_bfloat16* __restrict__ Wh, const __nv_bfloat16* __restrict__ Wl,
                float* __restrict__ Z, int K, int N,
                float* __restrict__ pS, float* __restrict__ pQ)
{
    constexpr int RB  = 80;        // smem row bytes (40 bf16: 32 data + 8 pad)
    constexpr int PL  = 128 * RB;  // plane bytes per stage: 10240
    constexpr int STG = 4 * PL;    // stage bytes: 40960

    extern __shared__ char dsm[];
    __shared__ float sPS[2][128];
    __shared__ float sPQ[2][128];

    const int tid  = threadIdx.x;
    const int lane = tid & 31;
    const int w    = tid >> 5;
    const int mb = blockIdx.y, nb = blockIdx.x;
    const int m0w = (w >> 2) * 64;   // warp M origin (0 or 64)
    const int n0w = (w & 3) * 32;    // warp N origin (0/32/64/96)

    const uint32_t sb = smem_u32(dsm);
    const size_t Abase = (size_t)mb * 128 * K;
    const size_t Bbase = (size_t)nb * 128 * K;
    const int NC = K / 32;

    // per-lane ldmatrix address components
    const int aRow = (lane & 7) + ((lane >> 3) & 1) * 8;
    const int aK   = ((lane >> 4) & 1) * 8;
    const uint32_t baseA = (uint32_t)((m0w + aRow) * RB + aK * 2);
    const int bRow = (lane & 7) + ((lane >> 4) & 1) * 8;
    const int bK   = ((lane >> 3) & 1) * 8;
    const uint32_t baseB = (uint32_t)((n0w + bRow) * RB + bK * 2);

    float acc[4][4][4];
#pragma unroll
    for (int mi = 0; mi < 4; mi++)
#pragma unroll
        for (int ni = 0; ni < 4; ni++)
#pragma unroll
            for (int c = 0; c < 4; c++) acc[mi][ni][c] = 0.0f;

    auto load_stage = [&](int ic) {
        const uint32_t st = sb + (uint32_t)(ic & 1) * STG;
        const int koff = ic * 32;
#pragma unroll
        for (int t = 0; t < 8; t++) {
            int u  = tid + t * 256;
            int pl = u >> 9;           // 0:Ah 1:Al 2:Wh 3:Wl
            int r  = (u >> 2) & 127;
            int j  = u & 3;
            uint32_t dst = st + (uint32_t)(pl * PL + r * RB + j * 16);
            const __nv_bfloat16* src;
            size_t goff;
            if (pl < 2) { src = (pl == 0) ? Ah : Al; goff = Abase + (size_t)r * K + koff + j * 8; }
            else        { src = (pl == 2) ? Wh : Wl; goff = Bbase + (size_t)r * K + koff + j * 8; }
            cpa16(dst, src + goff);
        }
        CP_COMMIT();
    };

    load_stage(0);
    load_stage(1);

    for (int ic = 0; ic < NC; ic++) {
        if (ic < NC - 1) asm volatile("cp.async.wait_group 1;" ::: "memory");
        else             asm volatile("cp.async.wait_group 0;" ::: "memory");
        __syncthreads();

        const uint32_t st = sb + (uint32_t)(ic & 1) * STG;
#pragma unroll
        for (int ks = 0; ks < 2; ks++) {
            const uint32_t ko = (uint32_t)(ks * 32);  // 16 bf16 = 32 bytes
            uint32_t ah[4][4], al[4][4], bh[2][4], bl[2][4];
#pragma unroll
            for (int mi = 0; mi < 4; mi++)
                LDSM4(ah[mi], st + 0 * PL + baseA + (uint32_t)(mi * 16 * RB) + ko);
#pragma unroll
            for (int nh = 0; nh < 2; nh++)
                LDSM4(bh[nh], st + 2 * PL + baseB + (uint32_t)(nh * 16 * RB) + ko);
#pragma unroll
            for (int mi = 0; mi < 4; mi++)
#pragma unroll
                for (int ni = 0; ni < 4; ni++)
                    MMA16816(acc[mi][ni], ah[mi], &bh[ni >> 1][(ni & 1) * 2]);
#pragma unroll
            for (int mi = 0; mi < 4; mi++)
                LDSM4(al[mi], st + 1 * PL + baseA + (uint32_t)(mi * 16 * RB) + ko);
#pragma unroll
            for (int mi = 0; mi < 4; mi++)
#pragma unroll
                for (int ni = 0; ni < 4; ni++)
                    MMA16816(acc[mi][ni], al[mi], &bh[ni >> 1][(ni & 1) * 2]);
#pragma unroll
            for (int nh = 0; nh < 2; nh++)
                LDSM4(bl[nh], st + 3 * PL + baseB + (uint32_t)(nh * 16 * RB) + ko);
#pragma unroll
            for (int mi = 0; mi < 4; mi++)
#pragma unroll
                for (int ni = 0; ni < 4; ni++)
                    MMA16816(acc[mi][ni], ah[mi], &bl[ni >> 1][(ni & 1) * 2]);
        }
        __syncthreads();
        if (ic + 2 < NC) load_stage(ic + 2);
    }

    // ------------- epilogue: accs -> smem -> coalesced Z + BN partials -------
    float* sO = reinterpret_cast<float*>(dsm);   // [128][132]
    const int grp = lane >> 2, t4 = lane & 3;
#pragma unroll
    for (int mi = 0; mi < 4; mi++) {
#pragma unroll
        for (int ni = 0; ni < 4; ni++) {
            int row = m0w + mi * 16 + grp;
            int col = n0w + ni * 8 + t4 * 2;
            sO[row * 132 + col]           = acc[mi][ni][0];
            sO[row * 132 + col + 1]       = acc[mi][ni][1];
            sO[(row + 8) * 132 + col]     = acc[mi][ni][2];
            sO[(row + 8) * 132 + col + 1] = acc[mi][ni][3];
        }
    }
    __syncthreads();

    // coalesced Z store: 128x128 floats as float4
#pragma unroll
    for (int t = 0; t < 16; t++) {
        int idx = tid + t * 256;
        int row = idx >> 5;
        int c4  = idx & 31;
        float4 v = *reinterpret_cast<float4*>(&sO[row * 132 + c4 * 4]);
        *reinterpret_cast<float4*>(
            &Z[(size_t)(mb * 128 + row) * N + nb * 128 + c4 * 4]) = v;
    }

    // deterministic BN partials over this 128-row block
    {
        int col = tid & 127, hf = tid >> 7;
        float S = 0.0f, Q = 0.0f;
#pragma unroll 8
        for (int r = 0; r < 64; r++) {
            float v = sO[(hf * 64 + r) * 132 + col];
            S += v; Q += v * v;
        }
        sPS[hf][col] = S; sPQ[hf][col] = Q;
    }
    __syncthreads();
    if (tid < 128) {
        pS[(size_t)mb * N + nb * 128 + tid] = sPS[0][tid] + sPS[1][tid];
        pQ[(size_t)mb * N + nb * 128 + tid] = sPQ[0][tid] + sPQ[1][tid];
    }
}

// ---------------------------------------------------------------------------
// Kernel 5: finalize BN stats -> per-channel (scale, shift)
// ---------------------------------------------------------------------------
__global__ void k_finalize(const float* __restrict__ pS, const float* __restrict__ pQ,
                           const float* __restrict__ gma, const float* __restrict__ bet,
                           float* __restrict__ scale, float* __restrict__ shift, int N)
{
    int c = blockIdx.x, tid = threadIdx.x;
    float S = 0, Q = 0;
    for (int m = tid; m < MBLK; m += 128) { S += pS[m * N + c]; Q += pQ[m * N + c]; }
    __shared__ float rs[128], rq[128];
    rs[tid] = S; rq[tid] = Q;
    __syncthreads();
    for (int off = 64; off > 0; off >>= 1) {
        if (tid < off) { rs[tid] += rs[tid + off]; rq[tid] += rq[tid + off]; }
        __syncthreads();
    }
    if (tid == 0) {
        float mean = rs[0] * (1.0f / NTOT);
        float var  = rq[0] * (1.0f / NTOT) - mean * mean;
        float sc   = gma[c] * rsqrtf(var + 1e-5f);
        scale[c] = sc;
        shift[c] = fmaf(-mean, sc, bet[c]);
    }
}

// ---------------------------------------------------------------------------
// Kernel 6: BN+ReLU on Z, split to next layer's (hi, lo) bf16 planes
// ---------------------------------------------------------------------------
__global__ void k_bnconv(const float* __restrict__ Zp, const float* __restrict__ sc,
                         const float* __restrict__ sh,
                         __nv_bfloat16* __restrict__ Ah, __nv_bfloat16* __restrict__ Al,
                         int N4, size_t total4)
{
    size_t i = (size_t)blockIdx.x * blockDim.x + threadIdx.x;
    if (i >= total4) return;
    int c4 = (int)(i % (size_t)N4);
    float4 v  = reinterpret_cast<const float4*>(Zp)[i];
    float4 s4 = reinterpret_cast<const float4*>(sc)[c4];
    float4 h4 = reinterpret_cast<const float4*>(sh)[c4];
    v.x = fmaxf(fmaf(v.x, s4.x, h4.x), 0.0f);
    v.y = fmaxf(fmaf(v.y, s4.y, h4.y), 0.0f);
    v.z = fmaxf(fmaf(v.z, s4.z, h4.z), 0.0f);
    v.w = fmaxf(fmaf(v.w, s4.w, h4.w), 0.0f);
    ushort4 hh, ll;
    bsplit(v.x, hh.x, ll.x); bsplit(v.y, hh.y, ll.y);
    bsplit(v.z, hh.z, ll.z); bsplit(v.w, hh.w, ll.w);
    reinterpret_cast<ushort4*>(Ah)[i] = hh;
    reinterpret_cast<ushort4*>(Al)[i] = ll;
}

// ---------------------------------------------------------------------------
// Kernel 7: BN3 + ReLU + transpose [n, c] -> out[b, c, n]
// ---------------------------------------------------------------------------
__global__ void k_out(const float* __restrict__ Z3, const float* __restrict__ scale,
                      const float* __restrict__ shift, float* __restrict__ out)
{
    __shared__ float tile[32][33];
    int b  = blockIdx.z;
    int n0 = blockIdx.x * 32, c0 = blockIdx.y * 32;
    int tx = threadIdx.x, ty = threadIdx.y;
    float sc = scale[c0 + tx], sh = shift[c0 + tx];
#pragma unroll
    for (int i = 0; i < 32; i += 8) {
        float v = Z3[((size_t)b * NYP + n0 + ty + i) * C3O + c0 + tx];
        tile[ty + i][tx] = fmaxf(fmaf(v, sc, sh), 0.0f);
    }
    __syncthreads();
#pragma unroll
    for (int i = 0; i < 32; i += 8)
        out[((size_t)b * C3O + c0 + ty + i) * NYP + n0 + tx] = tile[tx][ty + i];
}

// ---------------------------------------------------------------------------
// Launch
// ---------------------------------------------------------------------------
extern "C" void kernel_launch(void* const* d_in, const int* in_sizes, int n_in,
                              void* d_out, int out_size)
{
    const float* yp  = (const float*)d_in[0];
    const float* yf  = (const float*)d_in[1];
    const float* xp  = (const float*)d_in[2];
    const float* xf  = (const float*)d_in[3];
    const float* W1  = (const float*)d_in[4];
    const float* g1  = (const float*)d_in[6];
    const float* be1 = (const float*)d_in[7];
    const float* W2  = (const float*)d_in[8];
    const float* g2  = (const float*)d_in[10];
    const float* be2 = (const float*)d_in[11];
    const float* W3  = (const float*)d_in[12];
    const float* g3  = (const float*)d_in[14];
    const float* be3 = (const float*)d_in[15];
    float* out = (float*)d_out;

    __nv_bfloat16 *Ah, *Al, *Wh, *Wl;
    float *Z, *pS, *pQ, *SC, *SH;
    cudaGetSymbolAddress((void**)&Ah, g_Ah);
    cudaGetSymbolAddress((void**)&Al, g_Al);
    cudaGetSymbolAddress((void**)&Wh, g_Wh);
    cudaGetSymbolAddress((void**)&Wl, g_Wl);
    cudaGetSymbolAddress((void**)&Z,  g_Z);
    cudaGetSymbolAddress((void**)&pS, g_pS);
    cudaGetSymbolAddress((void**)&pQ, g_pQ);
    cudaGetSymbolAddress((void**)&SC, g_scale);
    cudaGetSymbolAddress((void**)&SH, g_shift);

    float* sc1 = SC + 0 * C1O;  float* sh1 = SH + 0 * C1O;
    float* sc2 = SC + 1 * C1O;  float* sh2 = SH + 1 * C1O;
    float* sc3 = SC + 2 * C1O;  float* sh3 = SH + 2 * C1O;

    const int SMG = 2 * 4 * 128 * 80;  // 81920 B dynamic smem
    cudaFuncSetAttribute(k_gemm_mma, cudaFuncAttributeMaxDynamicSharedMemorySize, SMG);

    const int O1 = 0, O2 = 512 * 384, O3 = 512 * 384 + 256 * 512;

    // 1) pack x points; split weights
    k_xw<<<(BB * NXP + 255) / 256, 256>>>(xp);
    k_wconv<<<(512 * 384 + 255) / 256, 256>>>(W1, Wh + O1, Wl + O1, 512 * 384);
    k_wconv<<<(256 * 512 + 255) / 256, 256>>>(W2, Wh + O2, Wl + O2, 256 * 512);
    k_wconv<<<(128 * 256 + 255) / 256, 256>>>(W3, Wh + O3, Wl + O3, 128 * 256);

    // 2) KNN + interpolate + concat -> A1 (hi/lo bf16, K=384)
    k_knn<<<dim3(NYP / KYPB, BB), KT>>>(yp, yf, xf);

    // 3) layer 1: GEMM -> Z [N=512], stats; finalize; BN+ReLU+split -> A2
    k_gemm_mma<<<dim3(C1O / 128, NTOT / 128), 256, SMG>>>(Ah, Al, Wh + O1, Wl + O1,
                                                          Z, DIMF, C1O, pS, pQ);
    k_finalize<<<C1O, 128>>>(pS, pQ, g1, be1, sc1, sh1, C1O);
    {
        size_t t4 = (size_t)NTOT * C1O / 4;
        k_bnconv<<<(unsigned)((t4 + 255) / 256), 256>>>(Z, sc1, sh1, Ah, Al, C1O / 4, t4);
    }

    // 4) layer 2
    k_gemm_mma<<<dim3(C2O / 128, NTOT / 128), 256, SMG>>>(Ah, Al, Wh + O2, Wl + O2,
                                                          Z, C1O, C2O, pS, pQ);
    k_finalize<<<C2O, 128>>>(pS, pQ, g2, be2, sc2, sh2, C2O);
    {
        size_t t4 = (size_t)NTOT * C2O / 4;
        k_bnconv<<<(unsigned)((t4 + 255) / 256), 256>>>(Z, sc2, sh2, Ah, Al, C2O / 4, t4);
    }

    // 5) layer 3
    k_gemm_mma<<<dim3(C3O / 128, NTOT / 128), 256, SMG>>>(Ah, Al, Wh + O3, Wl + O3,
                                                          Z, C2O, C3O, pS, pQ);
    k_finalize<<<C3O, 128>>>(pS, pQ, g3, be3, sc3, sh3, C3O);

    // 6) BN3 + ReLU + transpose -> out [B, 128, NY]
    k_out<<<dim3(NYP / 32, C3O / 32, BB), dim3(32, 8)>>>(Z, sc3, sh3, out);
}

// round 10
// speedup vs baseline: 2.9701x; 2.8185x over previous
#include <cuda_runtime.h>
#include <cuda_fp16.h>
#include <cstdint>
#include <cstddef>

// ---------------------------------------------------------------------------
// Problem constants
// ---------------------------------------------------------------------------
#define BB   4
#define NYP  16384
#define NXP  4096
#define CYF  128
#define CXF  256
#define DIMF 384         // CYF + CXF
#define C1O  512
#define C2O  256
#define C3O  128
#define NTOT (BB * NYP)  // 65536
#define MBLK (NTOT / 128) // 512 row-blocks for stats partials

// ---------------------------------------------------------------------------
// Scratch (static device globals — runtime alloc is forbidden)
// ---------------------------------------------------------------------------
__device__ __align__(16) __half g_A[(size_t)NTOT * 512];
__device__ __align__(16) float  g_Z[(size_t)NTOT * 512];
__device__ __align__(16) __half g_W[512*384 + 256*512 + 128*256];
__device__ __align__(16) float4 g_xw[BB * NXP];
__device__ __align__(16) float  g_pS[MBLK * C1O];
__device__ __align__(16) float  g_pQ[MBLK * C1O];
__device__ __align__(16) float  g_scale[3 * C1O];
__device__ __align__(16) float  g_shift[3 * C1O];

// ---------------------------------------------------------------------------
// PTX helpers (base compute_103-safe: no tcgen05)
// ---------------------------------------------------------------------------
__device__ __forceinline__ uint32_t smem_u32(const void* p) {
    uint32_t a;
    asm("{ .reg .u64 t; cvta.to.shared.u64 t, %1; cvt.u32.u64 %0, t; }" : "=r"(a) : "l"(p));
    return a;
}
__device__ __forceinline__ void cpa16(uint32_t dst, const void* src) {
    asm volatile("cp.async.cg.shared.global [%0], [%1], 16;" :: "r"(dst), "l"(src));
}
#define CP_COMMIT() asm volatile("cp.async.commit_group;" ::: "memory")

#define LDSM4(r, addr) \
    asm volatile("ldmatrix.sync.aligned.m8n8.x4.shared.b16 {%0,%1,%2,%3}, [%4];" \
        : "=r"((r)[0]), "=r"((r)[1]), "=r"((r)[2]), "=r"((r)[3]) : "r"(addr))

#define MMA16816(d, a, b) \
    asm volatile("mma.sync.aligned.m16n8k16.row.col.f32.f16.f16.f32 " \
        "{%0,%1,%2,%3}, {%4,%5,%6,%7}, {%8,%9}, {%0,%1,%2,%3};" \
        : "+f"((d)[0]), "+f"((d)[1]), "+f"((d)[2]), "+f"((d)[3]) \
        : "r"((a)[0]), "r"((a)[1]), "r"((a)[2]), "r"((a)[3]), \
          "r"((b)[0]), "r"((b)[1]))

__device__ __forceinline__ unsigned short h16(float v) {
    __half h = __float2half_rn(v);
    return *reinterpret_cast<unsigned short*>(&h);
}

// ---------------------------------------------------------------------------
// Kernel 1: pack x points as float4 (x, y, z, ||x||^2)
// ---------------------------------------------------------------------------
__global__ void k_xw(const float* __restrict__ xp)
{
    int i = blockIdx.x * blockDim.x + threadIdx.x;
    if (i < BB * NXP) {
        float x = xp[3 * i + 0];
        float y = xp[3 * i + 1];
        float z = xp[3 * i + 2];
        g_xw[i] = make_float4(x, y, z, x * x + y * y + z * z);
    }
}

// ---------------------------------------------------------------------------
// Kernel 2: brute-force 3-NN + interpolation + concat -> A1 (f16, K=384)
// One y point per thread (maximize warp parallelism / latency hiding).
// ---------------------------------------------------------------------------
#define KT   128
#define KYPB 128
#define XT   1024

__global__ __launch_bounds__(KT)
void k_knn(const float* __restrict__ yp,
           const float* __restrict__ yf,
           const float* __restrict__ xf)
{
    __shared__ float4 sx[XT];
    __shared__ float  sw[KYPB][3];
    __shared__ int    si[KYPB][3];

    const int b     = blockIdx.y;
    const int ybase = blockIdx.x * KYPB;
    const int tid   = threadIdx.x;

    const float* p = yp + ((size_t)b * NYP + ybase + tid) * 3;
    const float yx = p[0], yy = p[1], yz = p[2];
    float d0 = 3.0e38f, d1 = 3.0e38f, d2 = 3.0e38f;
    int   i0 = 0, i1 = 0, i2 = 0;

    for (int t0 = 0; t0 < NXP; t0 += XT) {
        __syncthreads();
        for (int j = tid; j < XT; j += KT)
            sx[j] = g_xw[b * NXP + t0 + j];
        __syncthreads();

#pragma unroll 4
        for (int j = 0; j < XT; j++) {
            float4 xq = sx[j];
            float t = yx * xq.x;
            t = fmaf(yy, xq.y, t);
            t = fmaf(yz, xq.z, t);
            float dd = fmaf(-2.0f, t, xq.w);
            if (dd < d2) {
                int jg = t0 + j;
                if (dd < d1) {
                    d2 = d1; i2 = i1;
                    if (dd < d0) {
                        d1 = d0; i1 = i0;
                        d0 = dd; i0 = jg;
                    } else {
                        d1 = dd; i1 = jg;
                    }
                } else {
                    d2 = dd; i2 = jg;
                }
            }
        }
    }

    {
        float cy = yx * yx + yy * yy + yz * yz;
        float w0 = 1.0f / (d0 + cy + 1e-8f);
        float w1 = 1.0f / (d1 + cy + 1e-8f);
        float w2 = 1.0f / (d2 + cy + 1e-8f);
        float inv = 1.0f / (w0 + w1 + w2);
        sw[tid][0] = w0 * inv; sw[tid][1] = w1 * inv; sw[tid][2] = w2 * inv;
        si[tid][0] = i0;       si[tid][1] = i1;       si[tid][2] = i2;
    }
    __syncthreads();

    const float4* yf4 = reinterpret_cast<const float4*>(yf) + (size_t)b * NYP * (CYF / 4);
    const float4* xf4 = reinterpret_cast<const float4*>(xf) + (size_t)b * NXP * (CXF / 4);
    const int C4Y = CYF / 4;   // 32
    const int C4  = DIMF / 4;  // 96

    for (int it = tid; it < KYPB * C4; it += KT) {
        int yl = it / C4;
        int c4 = it - yl * C4;
        float4 o;
        if (c4 < C4Y) {
            o = yf4[(size_t)(ybase + yl) * C4Y + c4];
        } else {
            int cc = c4 - C4Y;
            float w0 = sw[yl][0], w1 = sw[yl][1], w2 = sw[yl][2];
            float4 f0 = xf4[(size_t)si[yl][0] * (CXF / 4) + cc];
            float4 f1 = xf4[(size_t)si[yl][1] * (CXF / 4) + cc];
            float4 f2 = xf4[(size_t)si[yl][2] * (CXF / 4) + cc];
            o.x = w0 * f0.x + w1 * f1.x + w2 * f2.x;
            o.y = w0 * f0.y + w1 * f1.y + w2 * f2.y;
            o.z = w0 * f0.z + w1 * f1.z + w2 * f2.z;
            o.w = w0 * f0.w + w1 * f1.w + w2 * f2.w;
        }
        size_t nrow = (size_t)b * NYP + ybase + yl;
        ushort4 hv;
        hv.x = h16(o.x); hv.y = h16(o.y); hv.z = h16(o.z); hv.w = h16(o.w);
        reinterpret_cast<ushort4*>(g_A)[nrow * C4 + c4] = hv;
    }
}

// ---------------------------------------------------------------------------
// Kernel 3: weight convert fp32 -> f16
// ---------------------------------------------------------------------------
__global__ void k_wconv(const float* __restrict__ W, __half* __restrict__ Wo, int n)
{
    int i = blockIdx.x * blockDim.x + threadIdx.x;
    if (i < n)
        reinterpret_cast<unsigned short*>(Wo)[i] = h16(W[i]);
}

// ---------------------------------------------------------------------------
// Kernel 4: HMMA f16 GEMM (single pass, fp32 accum):  Z = A * W^T
// Tile 128x128, BK=32, 256 threads (8 warps, 2x4), warp tile 64x32.
// 3-stage cp.async pipeline (loads overlap MMA); epilogue through smem for
// coalesced Z stores + deterministic BN partial sums.
// ---------------------------------------------------------------------------
__global__ __launch_bounds__(256)
void k_gemm_mma(const __half* __restrict__ A, const __half* __restrict__ W,
                float* __restrict__ Z, int K, int N,
                float* __restrict__ pS, float* __restrict__ pQ)
{
    constexpr int RB  = 80;        // smem row bytes (32 f16 = 64 B data + 16 pad)
    constexpr int PL  = 128 * RB;  // plane bytes: 10240
    constexpr int STG = 2 * PL;    // stage bytes: 20480 (A plane + W plane)

    extern __shared__ char dsm[];
    __shared__ float sPS[2][128];
    __shared__ float sPQ[2][128];

    const int tid  = threadIdx.x;
    const int lane = tid & 31;
    const int w    = tid >> 5;
    const int mb = blockIdx.y, nb = blockIdx.x;
    const int m0w = (w >> 2) * 64;   // warp M origin (0 or 64)
    const int n0w = (w & 3) * 32;    // warp N origin (0/32/64/96)

    const uint32_t sb = smem_u32(dsm);
    const size_t Abase = (size_t)mb * 128 * K;
    const size_t Bbase = (size_t)nb * 128 * K;
    const int NC = K / 32;

    // per-lane ldmatrix address components
    const int aRow = (lane & 7) + ((lane >> 3) & 1) * 8;
    const int aK   = ((lane >> 4) & 1) * 8;
    const uint32_t baseA = (uint32_t)((m0w + aRow) * RB + aK * 2);
    const int bRow = (lane & 7) + ((lane >> 4) & 1) * 8;
    const int bK   = ((lane >> 3) & 1) * 8;
    const uint32_t baseB = (uint32_t)((n0w + bRow) * RB + bK * 2);

    float acc[4][4][4];
#pragma unroll
    for (int mi = 0; mi < 4; mi++)
#pragma unroll
        for (int ni = 0; ni < 4; ni++)
#pragma unroll
            for (int c = 0; c < 4; c++) acc[mi][ni][c] = 0.0f;

    auto load_stage = [&](int ic) {
        const uint32_t st = sb + (uint32_t)(ic % 3) * STG;
        const int koff = ic * 32;
#pragma unroll
        for (int t = 0; t < 4; t++) {
            int u  = tid + t * 256;        // 0..1023
            int pl = u >> 9;               // 0: A, 1: W
            int r  = (u >> 2) & 127;
            int j  = u & 3;
            uint32_t dst = st + (uint32_t)(pl * PL + r * RB + j * 16);
            const __half* src = pl ? W : A;
            size_t goff = (pl ? Bbase : Abase) + (size_t)r * K + koff + j * 8;
            cpa16(dst, src + goff);
        }
        CP_COMMIT();
    };

    load_stage(0);
    load_stage(1);

    for (int ic = 0; ic < NC; ic++) {
        if (ic < NC - 1) asm volatile("cp.async.wait_group 1;" ::: "memory");
        else             asm volatile("cp.async.wait_group 0;" ::: "memory");
        __syncthreads();

        if (ic + 2 < NC) load_stage(ic + 2);  // overlaps with MMA below

        const uint32_t st = sb + (uint32_t)(ic % 3) * STG;
#pragma unroll
        for (int ks = 0; ks < 2; ks++) {
            const uint32_t ko = (uint32_t)(ks * 32);  // 16 f16 = 32 bytes
            uint32_t ah[4][4], bh[2][4];
#pragma unroll
            for (int mi = 0; mi < 4; mi++)
                LDSM4(ah[mi], st + baseA + (uint32_t)(mi * 16 * RB) + ko);
#pragma unroll
            for (int nh = 0; nh < 2; nh++)
                LDSM4(bh[nh], st + PL + baseB + (uint32_t)(nh * 16 * RB) + ko);
#pragma unroll
            for (int mi = 0; mi < 4; mi++)
#pragma unroll
                for (int ni = 0; ni < 4; ni++)
                    MMA16816(acc[mi][ni], ah[mi], &bh[ni >> 1][(ni & 1) * 2]);
        }
    }
    __syncthreads();   // protect smem before epilogue reuse

    // ------------- epilogue: accs -> smem -> coalesced Z + BN partials -------
    float* sO = reinterpret_cast<float*>(dsm);   // [128][132]
    const int grp = lane >> 2, t4 = lane & 3;
#pragma unroll
    for (int mi = 0; mi < 4; mi++) {
#pragma unroll
        for (int ni = 0; ni < 4; ni++) {
            int row = m0w + mi * 16 + grp;
            int col = n0w + ni * 8 + t4 * 2;
            sO[row * 132 + col]           = acc[mi][ni][0];
            sO[row * 132 + col + 1]       = acc[mi][ni][1];
            sO[(row + 8) * 132 + col]     = acc[mi][ni][2];
            sO[(row + 8) * 132 + col + 1] = acc[mi][ni][3];
        }
    }
    __syncthreads();

    // coalesced Z store: 128x128 floats as float4
#pragma unroll
    for (int t = 0; t < 16; t++) {
        int idx = tid + t * 256;
        int row = idx >> 5;
        int c4  = idx & 31;
        float4 v = *reinterpret_cast<float4*>(&sO[row * 132 + c4 * 4]);
        *reinterpret_cast<float4*>(
            &Z[(size_t)(mb * 128 + row) * N + nb * 128 + c4 * 4]) = v;
    }

    // deterministic BN partials over this 128-row block
    {
        int col = tid & 127, hf = tid >> 7;
        float S = 0.0f, Q = 0.0f;
#pragma unroll 8
        for (int r = 0; r < 64; r++) {
            float v = sO[(hf * 64 + r) * 132 + col];
            S += v; Q += v * v;
        }
        sPS[hf][col] = S; sPQ[hf][col] = Q;
    }
    __syncthreads();
    if (tid < 128) {
        pS[(size_t)mb * N + nb * 128 + tid] = sPS[0][tid] + sPS[1][tid];
        pQ[(size_t)mb * N + nb * 128 + tid] = sPQ[0][tid] + sPQ[1][tid];
    }
}

// ---------------------------------------------------------------------------
// Kernel 5: finalize BN stats -> per-channel (scale, shift)
// ---------------------------------------------------------------------------
__global__ void k_finalize(const float* __restrict__ pS, const float* __restrict__ pQ,
                           const float* __restrict__ gma, const float* __restrict__ bet,
                           float* __restrict__ scale, float* __restrict__ shift, int N)
{
    int c = blockIdx.x, tid = threadIdx.x;
    float S = 0, Q = 0;
    for (int m = tid; m < MBLK; m += 128) { S += pS[m * N + c]; Q += pQ[m * N + c]; }
    __shared__ float rs[128], rq[128];
    rs[tid] = S; rq[tid] = Q;
    __syncthreads();
    for (int off = 64; off > 0; off >>= 1) {
        if (tid < off) { rs[tid] += rs[tid + off]; rq[tid] += rq[tid + off]; }
        __syncthreads();
    }
    if (tid == 0) {
        float mean = rs[0] * (1.0f / NTOT);
        float var  = rq[0] * (1.0f / NTOT) - mean * mean;
        float sc   = gma[c] * rsqrtf(var + 1e-5f);
        scale[c] = sc;
        shift[c] = fmaf(-mean, sc, bet[c]);
    }
}

// ---------------------------------------------------------------------------
// Kernel 6: BN+ReLU on Z, convert to next layer's f16 activations
// ---------------------------------------------------------------------------
__global__ void k_bnconv(const float* __restrict__ Zp, const float* __restrict__ sc,
                         const float* __restrict__ sh, __half* __restrict__ Ao,
                         int N4, size_t total4)
{
    size_t i = (size_t)blockIdx.x * blockDim.x + threadIdx.x;
    if (i >= total4) return;
    int c4 = (int)(i % (size_t)N4);
    float4 v  = reinterpret_cast<const float4*>(Zp)[i];
    float4 s4 = reinterpret_cast<const float4*>(sc)[c4];
    float4 h4 = reinterpret_cast<const float4*>(sh)[c4];
    ushort4 o;
    o.x = h16(fmaxf(fmaf(v.x, s4.x, h4.x), 0.0f));
    o.y = h16(fmaxf(fmaf(v.y, s4.y, h4.y), 0.0f));
    o.z = h16(fmaxf(fmaf(v.z, s4.z, h4.z), 0.0f));
    o.w = h16(fmaxf(fmaf(v.w, s4.w, h4.w), 0.0f));
    reinterpret_cast<ushort4*>(Ao)[i] = o;
}

// ---------------------------------------------------------------------------
// Kernel 7: BN3 + ReLU + transpose [n, c] -> out[b, c, n]
// ---------------------------------------------------------------------------
__global__ void k_out(const float* __restrict__ Z3, const float* __restrict__ scale,
                      const float* __restrict__ shift, float* __restrict__ out)
{
    __shared__ float tile[32][33];
    int b  = blockIdx.z;
    int n0 = blockIdx.x * 32, c0 = blockIdx.y * 32;
    int tx = threadIdx.x, ty = threadIdx.y;
    float sc = scale[c0 + tx], sh = shift[c0 + tx];
#pragma unroll
    for (int i = 0; i < 32; i += 8) {
        float v = Z3[((size_t)b * NYP + n0 + ty + i) * C3O + c0 + tx];
        tile[ty + i][tx] = fmaxf(fmaf(v, sc, sh), 0.0f);
    }
    __syncthreads();
#pragma unroll
    for (int i = 0; i < 32; i += 8)
        out[((size_t)b * C3O + c0 + ty + i) * NYP + n0 + tx] = tile[tx][ty + i];
}

// ---------------------------------------------------------------------------
// Launch
// ---------------------------------------------------------------------------
extern "C" void kernel_launch(void* const* d_in, const int* in_sizes, int n_in,
                              void* d_out, int out_size)
{
    const float* yp  = (const float*)d_in[0];
    const float* yf  = (const float*)d_in[1];
    const float* xp  = (const float*)d_in[2];
    const float* xf  = (const float*)d_in[3];
    const float* W1  = (const float*)d_in[4];
    const float* g1  = (const float*)d_in[6];
    const float* be1 = (const float*)d_in[7];
    const float* W2  = (const float*)d_in[8];
    const float* g2  = (const float*)d_in[10];
    const float* be2 = (const float*)d_in[11];
    const float* W3  = (const float*)d_in[12];
    const float* g3  = (const float*)d_in[14];
    const float* be3 = (const float*)d_in[15];
    float* out = (float*)d_out;

    __half *A, *W;
    float *Z, *pS, *pQ, *SC, *SH;
    cudaGetSymbolAddress((void**)&A,  g_A);
    cudaGetSymbolAddress((void**)&W,  g_W);
    cudaGetSymbolAddress((void**)&Z,  g_Z);
    cudaGetSymbolAddress((void**)&pS, g_pS);
    cudaGetSymbolAddress((void**)&pQ, g_pQ);
    cudaGetSymbolAddress((void**)&SC, g_scale);
    cudaGetSymbolAddress((void**)&SH, g_shift);

    float* sc1 = SC + 0 * C1O;  float* sh1 = SH + 0 * C1O;
    float* sc2 = SC + 1 * C1O;  float* sh2 = SH + 1 * C1O;
    float* sc3 = SC + 2 * C1O;  float* sh3 = SH + 2 * C1O;

    const int SMG = 128 * 132 * 4;  // 67584 B dynamic smem (>= 3*20480 pipeline)
    cudaFuncSetAttribute(k_gemm_mma, cudaFuncAttributeMaxDynamicSharedMemorySize, SMG);

    const int O1 = 0, O2 = 512 * 384, O3 = 512 * 384 + 256 * 512;

    // 1) pack x points; convert weights
    k_xw<<<(BB * NXP + 255) / 256, 256>>>(xp);
    k_wconv<<<(512 * 384 + 255) / 256, 256>>>(W1, W + O1, 512 * 384);
    k_wconv<<<(256 * 512 + 255) / 256, 256>>>(W2, W + O2, 256 * 512);
    k_wconv<<<(128 * 256 + 255) / 256, 256>>>(W3, W + O3, 128 * 256);

    // 2) KNN + interpolate + concat -> A1 (f16, K=384)
    k_knn<<<dim3(NYP / KYPB, BB), KT>>>(yp, yf, xf);

    // 3) layer 1: GEMM -> Z [N=512], stats; finalize; BN+ReLU+convert -> A2
    k_gemm_mma<<<dim3(C1O / 128, NTOT / 128), 256, SMG>>>(A, W + O1, Z, DIMF, C1O, pS, pQ);
    k_finalize<<<C1O, 128>>>(pS, pQ, g1, be1, sc1, sh1, C1O);
    {
        size_t t4 = (size_t)NTOT * C1O / 4;
        k_bnconv<<<(unsigned)((t4 + 255) / 256), 256>>>(Z, sc1, sh1, A, C1O / 4, t4);
    }

    // 4) layer 2
    k_gemm_mma<<<dim3(C2O / 128, NTOT / 128), 256, SMG>>>(A, W + O2, Z, C1O, C2O, pS, pQ);
    k_finalize<<<C2O, 128>>>(pS, pQ, g2, be2, sc2, sh2, C2O);
    {
        size_t t4 = (size_t)NTOT * C2O / 4;
        k_bnconv<<<(unsigned)((t4 + 255) / 256), 256>>>(Z, sc2, sh2, A, C2O / 4, t4);
    }

    // 5) layer 3
    k_gemm_mma<<<dim3(C3O / 128, NTOT / 128), 256, SMG>>>(A, W + O3, Z, C2O, C3O, pS, pQ);
    k_finalize<<<C3O, 128>>>(pS, pQ, g3, be3, sc3, sh3, C3O);

    // 6) BN3 + ReLU + transpose -> out [B, 128, NY]
    k_out<<<dim3(NYP / 32, C3O / 32, BB), dim3(32, 8)>>>(Z, sc3, sh3, out);
}

// round 15
// speedup vs baseline: 2.9974x; 1.0092x over previous
#include <cuda_runtime.h>
#include <cuda_fp16.h>
#include <cstdint>
#include <cstddef>

// ---------------------------------------------------------------------------
// Problem constants
// ---------------------------------------------------------------------------
#define BB   4
#define NYP  16384
#define NXP  4096
#define CYF  128
#define CXF  256
#define DIMF 384         // CYF + CXF
#define C1O  512
#define C2O  256
#define C3O  128
#define NTOT (BB * NYP)  // 65536
#define MBLK (NTOT / 128) // 512 row-blocks for stats partials

// ---------------------------------------------------------------------------
// Scratch (static device globals — runtime alloc is forbidden)
// ---------------------------------------------------------------------------
__device__ __align__(16) __half g_A[(size_t)NTOT * 512];
__device__ __align__(16) float  g_Z[(size_t)NTOT * 512];
__device__ __align__(16) __half g_W[512*384 + 256*512 + 128*256];
__device__ __align__(16) float4 g_xw[BB * NXP];
__device__ __align__(16) float  g_pS[MBLK * C1O];
__device__ __align__(16) float  g_pQ[MBLK * C1O];
__device__ __align__(16) float  g_scale[3 * C1O];
__device__ __align__(16) float  g_shift[3 * C1O];

// ---------------------------------------------------------------------------
// PTX helpers (base compute_103-safe: no tcgen05)
// ---------------------------------------------------------------------------
__device__ __forceinline__ uint32_t smem_u32(const void* p) {
    uint32_t a;
    asm("{ .reg .u64 t; cvta.to.shared.u64 t, %1; cvt.u32.u64 %0, t; }" : "=r"(a) : "l"(p));
    return a;
}
__device__ __forceinline__ void cpa16(uint32_t dst, const void* src) {
    asm volatile("cp.async.cg.shared.global [%0], [%1], 16;" :: "r"(dst), "l"(src));
}
#define CP_COMMIT() asm volatile("cp.async.commit_group;" ::: "memory")

#define LDSM4(r, addr) \
    asm volatile("ldmatrix.sync.aligned.m8n8.x4.shared.b16 {%0,%1,%2,%3}, [%4];" \
        : "=r"((r)[0]), "=r"((r)[1]), "=r"((r)[2]), "=r"((r)[3]) : "r"(addr))

#define MMA16816(d, a, b) \
    asm volatile("mma.sync.aligned.m16n8k16.row.col.f32.f16.f16.f32 " \
        "{%0,%1,%2,%3}, {%4,%5,%6,%7}, {%8,%9}, {%0,%1,%2,%3};" \
        : "+f"((d)[0]), "+f"((d)[1]), "+f"((d)[2]), "+f"((d)[3]) \
        : "r"((a)[0]), "r"((a)[1]), "r"((a)[2]), "r"((a)[3]), \
          "r"((b)[0]), "r"((b)[1]))

__device__ __forceinline__ unsigned short h16(float v) {
    __half h = __float2half_rn(v);
    return *reinterpret_cast<unsigned short*>(&h);
}

// ---------------------------------------------------------------------------
// Kernel 1: pack x points as float4 (x, y, z, ||x||^2)
//   NOTE: this exact formulation (and the matching dd chain in k_knn) is
//   load-bearing for accuracy — changing the rounding order perturbs top-3
//   neighbor selection at near-ties and blows up rel_err. Do not refactor.
// ---------------------------------------------------------------------------
__global__ void k_xw(const float* __restrict__ xp)
{
    int i = blockIdx.x * blockDim.x + threadIdx.x;
    if (i < BB * NXP) {
        float x = xp[3 * i + 0];
        float y = xp[3 * i + 1];
        float z = xp[3 * i + 2];
        g_xw[i] = make_float4(x, y, z, x * x + y * y + z * z);
    }
}

// ---------------------------------------------------------------------------
// Kernel 2: brute-force 3-NN + interpolation + concat -> A1 (f16, K=384)
// One y point per thread. dd arithmetic is byte-identical to the round-10
// passing kernel (mul + 2 FMA + fmaf(-2, t, w)).
// ---------------------------------------------------------------------------
#define KT   128
#define KYPB 128
#define XT   1024

__global__ __launch_bounds__(KT)
void k_knn(const float* __restrict__ yp,
           const float* __restrict__ yf,
           const float* __restrict__ xf)
{
    __shared__ float4 sx[XT];
    __shared__ float  sw[KYPB][3];
    __shared__ int    si[KYPB][3];

    const int b     = blockIdx.y;
    const int ybase = blockIdx.x * KYPB;
    const int tid   = threadIdx.x;

    const float* p = yp + ((size_t)b * NYP + ybase + tid) * 3;
    const float yx = p[0], yy = p[1], yz = p[2];
    float d0 = 3.0e38f, d1 = 3.0e38f, d2 = 3.0e38f;
    int   i0 = 0, i1 = 0, i2 = 0;

    for (int t0 = 0; t0 < NXP; t0 += XT) {
        __syncthreads();
        for (int j = tid; j < XT; j += KT)
            sx[j] = g_xw[b * NXP + t0 + j];
        __syncthreads();

#pragma unroll 8
        for (int j = 0; j < XT; j++) {
            float4 xq = sx[j];
            float t = yx * xq.x;
            t = fmaf(yy, xq.y, t);
            t = fmaf(yz, xq.z, t);
            float dd = fmaf(-2.0f, t, xq.w);
            if (dd < d2) {
                int jg = t0 + j;
                if (dd < d1) {
                    d2 = d1; i2 = i1;
                    if (dd < d0) {
                        d1 = d0; i1 = i0;
                        d0 = dd; i0 = jg;
                    } else {
                        d1 = dd; i1 = jg;
                    }
                } else {
                    d2 = dd; i2 = jg;
                }
            }
        }
    }

    {
        float cy = yx * yx + yy * yy + yz * yz;
        float w0 = 1.0f / (d0 + cy + 1e-8f);
        float w1 = 1.0f / (d1 + cy + 1e-8f);
        float w2 = 1.0f / (d2 + cy + 1e-8f);
        float inv = 1.0f / (w0 + w1 + w2);
        sw[tid][0] = w0 * inv; sw[tid][1] = w1 * inv; sw[tid][2] = w2 * inv;
        si[tid][0] = i0;       si[tid][1] = i1;       si[tid][2] = i2;
    }
    __syncthreads();

    const float4* yf4 = reinterpret_cast<const float4*>(yf) + (size_t)b * NYP * (CYF / 4);
    const float4* xf4 = reinterpret_cast<const float4*>(xf) + (size_t)b * NXP * (CXF / 4);
    const int C4Y = CYF / 4;   // 32
    const int C4  = DIMF / 4;  // 96

    for (int it = tid; it < KYPB * C4; it += KT) {
        int yl = it / C4;
        int c4 = it - yl * C4;
        float4 o;
        if (c4 < C4Y) {
            o = yf4[(size_t)(ybase + yl) * C4Y + c4];
        } else {
            int cc = c4 - C4Y;
            float w0 = sw[yl][0], w1 = sw[yl][1], w2 = sw[yl][2];
            float4 f0 = xf4[(size_t)si[yl][0] * (CXF / 4) + cc];
            float4 f1 = xf4[(size_t)si[yl][1] * (CXF / 4) + cc];
            float4 f2 = xf4[(size_t)si[yl][2] * (CXF / 4) + cc];
            o.x = w0 * f0.x + w1 * f1.x + w2 * f2.x;
            o.y = w0 * f0.y + w1 * f1.y + w2 * f2.y;
            o.z = w0 * f0.z + w1 * f1.z + w2 * f2.z;
            o.w = w0 * f0.w + w1 * f1.w + w2 * f2.w;
        }
        size_t nrow = (size_t)b * NYP + ybase + yl;
        ushort4 hv;
        hv.x = h16(o.x); hv.y = h16(o.y); hv.z = h16(o.z); hv.w = h16(o.w);
        reinterpret_cast<ushort4*>(g_A)[nrow * C4 + c4] = hv;
    }
}

// ---------------------------------------------------------------------------
// Kernel 3: convert all three weight matrices fp32 -> f16 in ONE launch
// ---------------------------------------------------------------------------
#define NW1 (512 * 384)
#define NW2 (256 * 512)
#define NW3 (128 * 256)
__global__ void k_wconv_all(const float* __restrict__ W1, const float* __restrict__ W2,
                            const float* __restrict__ W3, __half* __restrict__ Wo)
{
    int i = blockIdx.x * blockDim.x + threadIdx.x;
    float v;
    if (i < NW1)                  v = W1[i];
    else if (i < NW1 + NW2)       v = W2[i - NW1];
    else if (i < NW1 + NW2 + NW3) v = W3[i - NW1 - NW2];
    else return;
    reinterpret_cast<unsigned short*>(Wo)[i] = h16(v);
}

// ---------------------------------------------------------------------------
// Kernel 4: HMMA f16 GEMM (single pass, fp32 accum):  Z = A * W^T
// Tile 128x128, BK=32, 256 threads (8 warps, 2x4), warp tile 64x32.
// 3-stage cp.async pipeline; epilogue through smem for coalesced Z stores
// + deterministic BN partial sums.
// ---------------------------------------------------------------------------
__global__ __launch_bounds__(256)
void k_gemm_mma(const __half* __restrict__ A, const __half* __restrict__ W,
                float* __restrict__ Z, int K, int N,
                float* __restrict__ pS, float* __restrict__ pQ)
{
    constexpr int RB  = 80;        // smem row bytes (32 f16 = 64 B data + 16 pad)
    constexpr int PL  = 128 * RB;  // plane bytes: 10240
    constexpr int STG = 2 * PL;    // stage bytes: 20480 (A plane + W plane)

    extern __shared__ char dsm[];
    __shared__ float sPS[2][128];
    __shared__ float sPQ[2][128];

    const int tid  = threadIdx.x;
    const int lane = tid & 31;
    const int w    = tid >> 5;
    const int mb = blockIdx.y, nb = blockIdx.x;
    const int m0w = (w >> 2) * 64;   // warp M origin (0 or 64)
    const int n0w = (w & 3) * 32;    // warp N origin (0/32/64/96)

    const uint32_t sb = smem_u32(dsm);
    const size_t Abase = (size_t)mb * 128 * K;
    const size_t Bbase = (size_t)nb * 128 * K;
    const int NC = K / 32;

    // per-lane ldmatrix address components
    const int aRow = (lane & 7) + ((lane >> 3) & 1) * 8;
    const int aK   = ((lane >> 4) & 1) * 8;
    const uint32_t baseA = (uint32_t)((m0w + aRow) * RB + aK * 2);
    const int bRow = (lane & 7) + ((lane >> 4) & 1) * 8;
    const int bK   = ((lane >> 3) & 1) * 8;
    const uint32_t baseB = (uint32_t)((n0w + bRow) * RB + bK * 2);

    float acc[4][4][4];
#pragma unroll
    for (int mi = 0; mi < 4; mi++)
#pragma unroll
        for (int ni = 0; ni < 4; ni++)
#pragma unroll
            for (int c = 0; c < 4; c++) acc[mi][ni][c] = 0.0f;

    auto load_stage = [&](int ic) {
        const uint32_t st = sb + (uint32_t)(ic % 3) * STG;
        const int koff = ic * 32;
#pragma unroll
        for (int t = 0; t < 4; t++) {
            int u  = tid + t * 256;        // 0..1023
            int pl = u >> 9;               // 0: A, 1: W
            int r  = (u >> 2) & 127;
            int j  = u & 3;
            uint32_t dst = st + (uint32_t)(pl * PL + r * RB + j * 16);
            const __half* src = pl ? W : A;
            size_t goff = (pl ? Bbase : Abase) + (size_t)r * K + koff + j * 8;
            cpa16(dst, src + goff);
        }
        CP_COMMIT();
    };

    load_stage(0);
    load_stage(1);

    for (int ic = 0; ic < NC; ic++) {
        if (ic < NC - 1) asm volatile("cp.async.wait_group 1;" ::: "memory");
        else             asm volatile("cp.async.wait_group 0;" ::: "memory");
        __syncthreads();

        if (ic + 2 < NC) load_stage(ic + 2);  // overlaps with MMA below

        const uint32_t st = sb + (uint32_t)(ic % 3) * STG;
#pragma unroll
        for (int ks = 0; ks < 2; ks++) {
            const uint32_t ko = (uint32_t)(ks * 32);  // 16 f16 = 32 bytes
            uint32_t ah[4][4], bh[2][4];
#pragma unroll
            for (int mi = 0; mi < 4; mi++)
                LDSM4(ah[mi], st + baseA + (uint32_t)(mi * 16 * RB) + ko);
#pragma unroll
            for (int nh = 0; nh < 2; nh++)
                LDSM4(bh[nh], st + PL + baseB + (uint32_t)(nh * 16 * RB) + ko);
#pragma unroll
            for (int mi = 0; mi < 4; mi++)
#pragma unroll
                for (int ni = 0; ni < 4; ni++)
                    MMA16816(acc[mi][ni], ah[mi], &bh[ni >> 1][(ni & 1) * 2]);
        }
    }
    __syncthreads();   // protect smem before epilogue reuse

    // ------------- epilogue: accs -> smem -> coalesced Z + BN partials -------
    float* sO = reinterpret_cast<float*>(dsm);   // [128][132]
    const int grp = lane >> 2, t4 = lane & 3;
#pragma unroll
    for (int mi = 0; mi < 4; mi++) {
#pragma unroll
        for (int ni = 0; ni < 4; ni++) {
            int row = m0w + mi * 16 + grp;
            int col = n0w + ni * 8 + t4 * 2;
            sO[row * 132 + col]           = acc[mi][ni][0];
            sO[row * 132 + col + 1]       = acc[mi][ni][1];
            sO[(row + 8) * 132 + col]     = acc[mi][ni][2];
            sO[(row + 8) * 132 + col + 1] = acc[mi][ni][3];
        }
    }
    __syncthreads();

    // coalesced Z store: 128x128 floats as float4
#pragma unroll
    for (int t = 0; t < 16; t++) {
        int idx = tid + t * 256;
        int row = idx >> 5;
        int c4  = idx & 31;
        float4 v = *reinterpret_cast<float4*>(&sO[row * 132 + c4 * 4]);
        *reinterpret_cast<float4*>(
            &Z[(size_t)(mb * 128 + row) * N + nb * 128 + c4 * 4]) = v;
    }

    // deterministic BN partials over this 128-row block
    {
        int col = tid & 127, hf = tid >> 7;
        float S = 0.0f, Q = 0.0f;
#pragma unroll 8
        for (int r = 0; r < 64; r++) {
            float v = sO[(hf * 64 + r) * 132 + col];
            S += v; Q += v * v;
        }
        sPS[hf][col] = S; sPQ[hf][col] = Q;
    }
    __syncthreads();
    if (tid < 128) {
        pS[(size_t)mb * N + nb * 128 + tid] = sPS[0][tid] + sPS[1][tid];
        pQ[(size_t)mb * N + nb * 128 + tid] = sPQ[0][tid] + sPQ[1][tid];
    }
}

// ---------------------------------------------------------------------------
// Kernel 5: finalize BN stats -> per-channel (scale, shift)
// ---------------------------------------------------------------------------
__global__ void k_finalize(const float* __restrict__ pS, const float* __restrict__ pQ,
                           const float* __restrict__ gma, const float* __restrict__ bet,
                           float* __restrict__ scale, float* __restrict__ shift, int N)
{
    int c = blockIdx.x, tid = threadIdx.x;
    float S = 0, Q = 0;
    for (int m = tid; m < MBLK; m += 128) { S += pS[m * N + c]; Q += pQ[m * N + c]; }
    __shared__ float rs[128], rq[128];
    rs[tid] = S; rq[tid] = Q;
    __syncthreads();
    for (int off = 64; off > 0; off >>= 1) {
        if (tid < off) { rs[tid] += rs[tid + off]; rq[tid] += rq[tid + off]; }
        __syncthreads();
    }
    if (tid == 0) {
        float mean = rs[0] * (1.0f / NTOT);
        float var  = rq[0] * (1.0f / NTOT) - mean * mean;
        float sc   = gma[c] * rsqrtf(var + 1e-5f);
        scale[c] = sc;
        shift[c] = fmaf(-mean, sc, bet[c]);
    }
}

// ---------------------------------------------------------------------------
// Kernel 6: BN+ReLU on Z, convert to next layer's f16 activations
// ---------------------------------------------------------------------------
__global__ void k_bnconv(const float* __restrict__ Zp, const float* __restrict__ sc,
                         const float* __restrict__ sh, __half* __restrict__ Ao,
                         int N4, size_t total4)
{
    size_t i = (size_t)blockIdx.x * blockDim.x + threadIdx.x;
    if (i >= total4) return;
    int c4 = (int)(i % (size_t)N4);
    float4 v  = reinterpret_cast<const float4*>(Zp)[i];
    float4 s4 = reinterpret_cast<const float4*>(sc)[c4];
    float4 h4 = reinterpret_cast<const float4*>(sh)[c4];
    ushort4 o;
    o.x = h16(fmaxf(fmaf(v.x, s4.x, h4.x), 0.0f));
    o.y = h16(fmaxf(fmaf(v.y, s4.y, h4.y), 0.0f));
    o.z = h16(fmaxf(fmaf(v.z, s4.z, h4.z), 0.0f));
    o.w = h16(fmaxf(fmaf(v.w, s4.w, h4.w), 0.0f));
    reinterpret_cast<ushort4*>(Ao)[i] = o;
}

// ---------------------------------------------------------------------------
// Kernel 7: BN3 + ReLU + transpose [n, c] -> out[b, c, n]
// ---------------------------------------------------------------------------
__global__ void k_out(const float* __restrict__ Z3, const float* __restrict__ scale,
                      const float* __restrict__ shift, float* __restrict__ out)
{
    __shared__ float tile[32][33];
    int b  = blockIdx.z;
    int n0 = blockIdx.x * 32, c0 = blockIdx.y * 32;
    int tx = threadIdx.x, ty = threadIdx.y;
    float sc = scale[c0 + tx], sh = shift[c0 + tx];
#pragma unroll
    for (int i = 0; i < 32; i += 8) {
        float v = Z3[((size_t)b * NYP + n0 + ty + i) * C3O + c0 + tx];
        tile[ty + i][tx] = fmaxf(fmaf(v, sc, sh), 0.0f);
    }
    __syncthreads();
#pragma unroll
    for (int i = 0; i < 32; i += 8)
        out[((size_t)b * C3O + c0 + ty + i) * NYP + n0 + tx] = tile[tx][ty + i];
}

// ---------------------------------------------------------------------------
// Launch
// ---------------------------------------------------------------------------
extern "C" void kernel_launch(void* const* d_in, const int* in_sizes, int n_in,
                              void* d_out, int out_size)
{
    const float* yp  = (const float*)d_in[0];
    const float* yf  = (const float*)d_in[1];
    const float* xp  = (const float*)d_in[2];
    const float* xf  = (const float*)d_in[3];
    const float* W1  = (const float*)d_in[4];
    const float* g1  = (const float*)d_in[6];
    const float* be1 = (const float*)d_in[7];
    const float* W2  = (const float*)d_in[8];
    const float* g2  = (const float*)d_in[10];
    const float* be2 = (const float*)d_in[11];
    const float* W3  = (const float*)d_in[12];
    const float* g3  = (const float*)d_in[14];
    const float* be3 = (const float*)d_in[15];
    float* out = (float*)d_out;

    __half *A, *W;
    float *Z, *pS, *pQ, *SC, *SH;
    cudaGetSymbolAddress((void**)&A,  g_A);
    cudaGetSymbolAddress((void**)&W,  g_W);
    cudaGetSymbolAddress((void**)&Z,  g_Z);
    cudaGetSymbolAddress((void**)&pS, g_pS);
    cudaGetSymbolAddress((void**)&pQ, g_pQ);
    cudaGetSymbolAddress((void**)&SC, g_scale);
    cudaGetSymbolAddress((void**)&SH, g_shift);

    float* sc1 = SC + 0 * C1O;  float* sh1 = SH + 0 * C1O;
    float* sc2 = SC + 1 * C1O;  float* sh2 = SH + 1 * C1O;
    float* sc3 = SC + 2 * C1O;  float* sh3 = SH + 2 * C1O;

    const int SMG = 128 * 132 * 4;  // 67584 B dynamic smem (>= 3*20480 pipeline)
    cudaFuncSetAttribute(k_gemm_mma, cudaFuncAttributeMaxDynamicSharedMemorySize, SMG);

    const int O1 = 0, O2 = 512 * 384, O3 = 512 * 384 + 256 * 512;

    // 1) pack x points; convert all weights in one launch
    k_xw<<<(BB * NXP + 255) / 256, 256>>>(xp);
    k_wconv_all<<<(NW1 + NW2 + NW3 + 255) / 256, 256>>>(W1, W2, W3, W);

    // 2) KNN + interpolate + concat -> A1 (f16, K=384)
    k_knn<<<dim3(NYP / KYPB, BB), KT>>>(yp, yf, xf);

    // 3) layer 1: GEMM -> Z [N=512], stats; finalize; BN+ReLU+convert -> A2
    k_gemm_mma<<<dim3(C1O / 128, NTOT / 128), 256, SMG>>>(A, W + O1, Z, DIMF, C1O, pS, pQ);
    k_finalize<<<C1O, 128>>>(pS, pQ, g1, be1, sc1, sh1, C1O);
    {
        size_t t4 = (size_t)NTOT * C1O / 4;
        k_bnconv<<<(unsigned)((t4 + 255) / 256), 256>>>(Z, sc1, sh1, A, C1O / 4, t4);
    }

    // 4) layer 2
    k_gemm_mma<<<dim3(C2O / 128, NTOT / 128), 256, SMG>>>(A, W + O2, Z, C1O, C2O, pS, pQ);
    k_finalize<<<C2O, 128>>>(pS, pQ, g2, be2, sc2, sh2, C2O);
    {
        size_t t4 = (size_t)NTOT * C2O / 4;
        k_bnconv<<<(unsigned)((t4 + 255) / 256), 256>>>(Z, sc2, sh2, A, C2O / 4, t4);
    }

    // 5) layer 3
    k_gemm_mma<<<dim3(C3O / 128, NTOT / 128), 256, SMG>>>(A, W + O3, Z, C2O, C3O, pS, pQ);
    k_finalize<<<C3O, 128>>>(pS, pQ, g3, be3, sc3, sh3, C3O);

    // 6) BN3 + ReLU + transpose -> out [B, 128, NY]
    k_out<<<dim3(NYP / 32, C3O / 32, BB), dim3(32, 8)>>>(Z, sc3, sh3, out);
}